// round 14
// baseline (speedup 1.0000x reference)
#include <cuda_runtime.h>
#include <cuda_bf16.h>
#include <math.h>
#include <stdint.h>

#define NNODES 20000
#define NEDGES 100000
#define DNODE 1280
#define DEDGE 505
#define DEDGE_PAD 512
#define NH 20
#define AEMB 1280
#define FF 5120

// ---------------- static device scratch ----------------
__device__ __nv_bfloat16 g_G1b[(size_t)NNODES * AEMB];
__device__ __nv_bfloat16 g_G2b[(size_t)NNODES * AEMB];
__device__ __nv_bfloat16 g_hb [(size_t)NNODES * DNODE];
__device__ __nv_bfloat16 g_ecb[(size_t)NEDGES * DEDGE_PAD];
__device__ float g_ecp[(size_t)NEDGES * DEDGE_PAD];   // fp32 padded (16B-aligned rows)
__device__ __nv_bfloat16 g_Wt1[(size_t)AEMB * DNODE];
__device__ __nv_bfloat16 g_Wt2[(size_t)AEMB * DNODE];
__device__ __nv_bfloat16 g_Wte[(size_t)AEMB * DEDGE_PAD];
__device__ float g_Wap1[DNODE * 64];
__device__ float g_Wap2[DNODE * 64];
__device__ float g_Wape[DEDGE_PAD * 64];
__device__ float g_a1[(size_t)NNODES * 64];
__device__ float g_a2[(size_t)NNODES * 64];
__device__ float g_ae[(size_t)NEDGES * 64];
__device__ float g_w [NEDGES * NH];
__device__ float g_gf[AEMB];
__device__ float g_y1[FF];
__device__ float g_y2[AEMB];
__device__ float g_smax[NH];
__device__ float g_sden[NH];
__device__ int   g_src[NEDGES];
__device__ int   g_dst[NEDGES];
__device__ int   g_idx64;

// ---------------- index dtype sniffing ----------------
__global__ void k_idx_mode(const int* __restrict__ raw) {
    if (blockIdx.x == 0 && threadIdx.x == 0) {
        int is64 = 1;
        for (int s = 0; s < 64; s++)
            if (raw[2 * s + 1] != 0) { is64 = 0; break; }
        g_idx64 = is64;
    }
}

__global__ void k_cvt_idx(const int* __restrict__ raw) {
    int e = blockIdx.x * blockDim.x + threadIdx.x;
    if (e >= NEDGES) return;
    if (g_idx64) { g_src[e] = raw[2 * e]; g_dst[e] = raw[2 * (NEDGES + e)]; }
    else         { g_src[e] = raw[e];     g_dst[e] = raw[NEDGES + e]; }
}

// ---------------- conversions / padding ----------------
// edge_core -> bf16 (padded) AND fp32 (padded) in one pass
__global__ __launch_bounds__(256) void k_ec2bf(const float* __restrict__ ec) {
    int t = blockIdx.x * blockDim.x + threadIdx.x;   // pair index
    if (t >= NEDGES * (DEDGE_PAD / 2)) return;
    int e = t >> 8, p = t & 255;
    int c = p * 2;
    const float* row = ec + (size_t)e * DEDGE;
    float x = (c     < DEDGE) ? row[c]     : 0.f;
    float y = (c + 1 < DEDGE) ? row[c + 1] : 0.f;
    __nv_bfloat162 v; v.x = __float2bfloat16(x); v.y = __float2bfloat16(y);
    *reinterpret_cast<__nv_bfloat162*>(g_ecb + (size_t)e * DEDGE_PAD + c) = v;
    *reinterpret_cast<float2*>(g_ecp + (size_t)e * DEDGE_PAD + c) = make_float2(x, y);
}

__global__ __launch_bounds__(256) void k_h2bf(const float* __restrict__ h) {
    int t = blockIdx.x * blockDim.x + threadIdx.x;   // float4 index
    if (t >= NNODES * DNODE / 4) return;
    float4 v = reinterpret_cast<const float4*>(h)[t];
    __nv_bfloat162 a, b;
    a.x = __float2bfloat16(v.x); a.y = __float2bfloat16(v.y);
    b.x = __float2bfloat16(v.z); b.y = __float2bfloat16(v.w);
    __nv_bfloat162* dst = reinterpret_cast<__nv_bfloat162*>(g_hb) + t * 2;
    dst[0] = a; dst[1] = b;
}

// transpose+convert W_node slice -> Wt[1280][Kpad] bf16
__global__ void k_wt(const float* __restrict__ W, __nv_bfloat16* __restrict__ Wt,
                     int Ksrc, int Kpad) {
    __shared__ float tile[32][33];
    int kb = blockIdx.x * 32, nb = blockIdx.y * 32;
    int tx = threadIdx.x, ty = threadIdx.y;   // 32 x 8
    for (int r = ty; r < 32; r += 8) {
        int k = kb + r;
        tile[r][tx] = (k < Ksrc) ? W[(size_t)k * AEMB + nb + tx] : 0.f;
    }
    __syncthreads();
    for (int r = ty; r < 32; r += 8) {
        int n = nb + r, k = kb + tx;
        if (k < Kpad) Wt[(size_t)n * Kpad + k] = __float2bfloat16(tile[tx][r]);
    }
}

// pack W_att slices into zero-padded [K][64] fp32 buffers
__global__ void k_wap(const float* __restrict__ W_att) {
    int t = blockIdx.x * blockDim.x + threadIdx.x;
    if (t >= DNODE * 64) return;
    int k = t >> 6, hh = t & 63;
    g_Wap1[t] = (hh < NH) ? W_att[(size_t)k * NH + hh] : 0.f;
    g_Wap2[t] = (hh < NH) ? W_att[(size_t)(DNODE + DEDGE + k) * NH + hh] : 0.f;
    if (k < DEDGE_PAD)
        g_Wape[t] = (hh < NH && k < DEDGE) ? W_att[(size_t)(DNODE + k) * NH + hh] : 0.f;
}

// ---------------- shared low-level helpers ----------------
__device__ __forceinline__ void cp16(unsigned dst, const void* src, int valid) {
    asm volatile("cp.async.cg.shared.global [%0], [%1], 16, %2;"
                 :: "r"(dst), "l"(src), "r"(valid));
}
__device__ __forceinline__ unsigned f2tf(float x) {
    unsigned u; asm("cvt.rna.tf32.f32 %0, %1;" : "=r"(u) : "f"(x)); return u;
}

// ---------------- tf32 tensor-core GEMM body (att logits): C[M,64] = A @ B ------
#define BM 128
#define BN 64
#define BK 32

#define MMA8(d, a, b) asm volatile( \
    "mma.sync.aligned.m16n8k8.row.col.f32.tf32.tf32.f32 " \
    "{%0,%1,%2,%3}, {%4,%5,%6,%7}, {%8,%9}, {%0,%1,%2,%3};" \
    : "+f"(d[0]), "+f"(d[1]), "+f"(d[2]), "+f"(d[3]) \
    : "r"(a[0]), "r"(a[1]), "r"(a[2]), "r"(a[3]), "r"(b[0]), "r"(b[1]))

__device__ __forceinline__ void tf32_body(
    const float* __restrict__ A, const float* __restrict__ B, float* __restrict__ C,
    int M, int K, int lda, int bm)
{
    __shared__ float sA[2][BM * BK];
    __shared__ float sB[2][BK * BN];

    const int tid = threadIdx.x;
    const int w = tid >> 5, lane = tid & 31;
    const int wm = (w >> 1) * 32;
    const int wn = (w & 1) * 32;
    const int g = lane >> 2, t = lane & 3;

    float acc[2][4][4];
#pragma unroll
    for (int mf = 0; mf < 2; mf++)
#pragma unroll
        for (int nf = 0; nf < 4; nf++)
#pragma unroll
            for (int q = 0; q < 4; q++) acc[mf][nf][q] = 0.f;

    const int nK = (K + BK - 1) / BK;

    auto loadA = [&](int kt, int s) {
#pragma unroll
        for (int p = 0; p < 4; p++) {
            int m  = (tid >> 3) + p * 32;
            int k4 = (tid & 7) * 4;
            int gm = bm + m;
            int gk = kt * BK + k4;
            int chunk = m * BK + (k4 ^ ((m & 7) << 2));
            int rem = K - gk;
            int valid = (gm < M) ? (rem >= 4 ? 16 : (rem > 0 ? rem * 4 : 0)) : 0;
            const float* src = (valid > 0) ? (A + (size_t)gm * lda + gk) : A;
            cp16((unsigned)__cvta_generic_to_shared(&sA[s][chunk]), src, valid);
        }
    };
    auto loadB = [&](int kt, int s) {
#pragma unroll
        for (int p = 0; p < 2; p++) {
            int k  = (tid >> 4) + p * 16;
            int n4 = (tid & 15) * 4;
            int gk = kt * BK + k;
            int valid = (gk < K) ? 16 : 0;
            const float* src = (valid > 0) ? (B + (size_t)gk * 64 + n4) : B;
            unsigned dst = (unsigned)__cvta_generic_to_shared(
                &sB[s][k * BN + (n4 ^ ((k & 3) << 3))]);
            cp16(dst, src, valid);
        }
    };

    loadA(0, 0); loadB(0, 0);
    asm volatile("cp.async.commit_group;");

    for (int kt = 0; kt < nK; kt++) {
        int cur = kt & 1, nxt = cur ^ 1;
        if (kt + 1 < nK) {
            loadA(kt + 1, nxt); loadB(kt + 1, nxt);
            asm volatile("cp.async.commit_group;");
            asm volatile("cp.async.wait_group 1;");
        } else {
            asm volatile("cp.async.wait_group 0;");
        }
        __syncthreads();

#pragma unroll
        for (int ks = 0; ks < 4; ks++) {
            unsigned a[2][4], b[4][2];
            int c0 = ks * 8 + t, c1 = c0 + 4;
#pragma unroll
            for (int mf = 0; mf < 2; mf++) {
                int r0 = wm + mf * 16 + g, r1 = r0 + 8;
                int s0 = (r0 & 7) << 2, s1 = (r1 & 7) << 2;
                a[mf][0] = f2tf(sA[cur][r0 * BK + (c0 ^ s0)]);
                a[mf][1] = f2tf(sA[cur][r1 * BK + (c0 ^ s1)]);
                a[mf][2] = f2tf(sA[cur][r0 * BK + (c1 ^ s0)]);
                a[mf][3] = f2tf(sA[cur][r1 * BK + (c1 ^ s1)]);
            }
            int kr0 = ks * 8 + t, kr1 = kr0 + 4;
            int sw = (t & 3) << 3;
#pragma unroll
            for (int nf = 0; nf < 4; nf++) {
                int n = wn + nf * 8 + g;
                b[nf][0] = f2tf(sB[cur][kr0 * BN + (n ^ sw)]);
                b[nf][1] = f2tf(sB[cur][kr1 * BN + (n ^ sw)]);
            }
#pragma unroll
            for (int mf = 0; mf < 2; mf++)
#pragma unroll
                for (int nf = 0; nf < 4; nf++)
                    MMA8(acc[mf][nf], a[mf], b[nf]);
        }
        __syncthreads();
    }

#pragma unroll
    for (int mf = 0; mf < 2; mf++) {
        int r0 = bm + wm + mf * 16 + g, r1 = r0 + 8;
#pragma unroll
        for (int nf = 0; nf < 4; nf++) {
            int cn = wn + nf * 8 + t * 2;
            if (r0 < M) {
                float2 v = make_float2(acc[mf][nf][0], acc[mf][nf][1]);
                *reinterpret_cast<float2*>(C + (size_t)r0 * 64 + cn) = v;
            }
            if (r1 < M) {
                float2 v = make_float2(acc[mf][nf][2], acc[mf][nf][3]);
                *reinterpret_cast<float2*>(C + (size_t)r1 * 64 + cn) = v;
            }
        }
    }
}

// single-matrix variant (edge att logits)
__global__ __launch_bounds__(256, 2) void k_mma_tf32s(
    const float* __restrict__ A, const float* __restrict__ B, float* __restrict__ C,
    int M, int K, int lda)
{
    tf32_body(A, B, C, M, K, lda, blockIdx.y * BM);
}

// dual variant: both node att-logit GEMMs in one launch (shared A = h)
__global__ __launch_bounds__(256, 2) void k_mma_tf32d(
    const float* __restrict__ A,
    const float* __restrict__ B1, const float* __restrict__ B2,
    float* __restrict__ C1, float* __restrict__ C2,
    int M, int K, int lda)
{
    const float* B = (blockIdx.x == 0) ? B1 : B2;
    float* C = (blockIdx.x == 0) ? C1 : C2;
    tf32_body(A, B, C, M, K, lda, blockIdx.y * BM);
}

// ---------------- bf16 tensor-core GEMM core (scalar-LDS fragments, 3-stage) -----
#define BN2 128
#define BKB 32
#define NST 3

#define MMA16(d, a, b) asm volatile( \
    "mma.sync.aligned.m16n8k16.row.col.f32.bf16.bf16.f32 " \
    "{%0,%1,%2,%3}, {%4,%5,%6,%7}, {%8,%9}, {%0,%1,%2,%3};" \
    : "+f"(d[0]), "+f"(d[1]), "+f"(d[2]), "+f"(d[3]) \
    : "r"(a[0]), "r"(a[1]), "r"(a[2]), "r"(a[3]), "r"(b[0]), "r"(b[1]))

struct MmaCtx {
    int tid, bm, bn, wm, wn, g, t;
};

__device__ __forceinline__ void bf16_mainloop(
    const __nv_bfloat16* __restrict__ A, const __nv_bfloat16* __restrict__ Bt,
    int M, int K, int lda, const MmaCtx& cx,
    uint32_t (*sA)[BM * 16], uint32_t (*sB)[BN2 * 16],
    float acc[2][8][4])
{
    const int tid = cx.tid, bm = cx.bm, bn = cx.bn;
    const int wm = cx.wm, wn = cx.wn, g = cx.g, t = cx.t;

    const int nK = K / BKB;

    auto loadA = [&](int kt, int s) {
#pragma unroll
        for (int p = 0; p < 2; p++) {
            int idx = tid + p * 256;
            int m = idx >> 2, c4 = idx & 3;
            int gm = bm + m;
            int valid = (gm < M) ? 16 : 0;
            const __nv_bfloat16* src = (valid > 0)
                ? (A + (size_t)gm * lda + kt * BKB + c4 * 8) : A;
            unsigned dst = (unsigned)__cvta_generic_to_shared(
                &sA[s][m * 16 + (c4 ^ ((m >> 1) & 3)) * 4]);
            cp16(dst, src, valid);
        }
    };
    auto loadB = [&](int kt, int s) {
#pragma unroll
        for (int p = 0; p < 2; p++) {
            int idx = tid + p * 256;
            int n = idx >> 2, c4 = idx & 3;
            const __nv_bfloat16* src = Bt + (size_t)(bn + n) * K + kt * BKB + c4 * 8;
            unsigned dst = (unsigned)__cvta_generic_to_shared(
                &sB[s][n * 16 + (c4 ^ ((n >> 1) & 3)) * 4]);
            cp16(dst, src, 16);
        }
    };

    loadA(0, 0); loadB(0, 0);
    asm volatile("cp.async.commit_group;");
    if (1 < nK) {
        loadA(1, 1); loadB(1, 1);
        asm volatile("cp.async.commit_group;");
    }

    int s_comp = 0, s_load = 2;

    for (int kt = 0; kt < nK; kt++) {
        if (kt == nK - 1) { asm volatile("cp.async.wait_group 0;"); }
        else              { asm volatile("cp.async.wait_group 1;"); }
        __syncthreads();

        if (kt + 2 < nK) {
            loadA(kt + 2, s_load); loadB(kt + 2, s_load);
            asm volatile("cp.async.commit_group;");
            if (++s_load == NST) s_load = 0;
        }

        int cur = s_comp;
#pragma unroll
        for (int ks = 0; ks < 2; ks++) {
            uint32_t a[2][4], b[8][2];
            int w0 = t + ks * 8, w1 = t + 4 + ks * 8;
#pragma unroll
            for (int mf = 0; mf < 2; mf++) {
                int r0 = wm + mf * 16 + g, r1 = r0 + 8;
                int s0 = ((r0 >> 1) & 3) << 2;
                a[mf][0] = sA[cur][r0 * 16 + (w0 ^ s0)];
                a[mf][1] = sA[cur][r1 * 16 + (w0 ^ s0)];
                a[mf][2] = sA[cur][r0 * 16 + (w1 ^ s0)];
                a[mf][3] = sA[cur][r1 * 16 + (w1 ^ s0)];
            }
#pragma unroll
            for (int nf = 0; nf < 8; nf++) {
                int n0 = wn + nf * 8 + g;
                int sn = ((n0 >> 1) & 3) << 2;
                b[nf][0] = sB[cur][n0 * 16 + (w0 ^ sn)];
                b[nf][1] = sB[cur][n0 * 16 + (w1 ^ sn)];
            }
#pragma unroll
            for (int mf = 0; mf < 2; mf++)
#pragma unroll
                for (int nf = 0; nf < 8; nf++)
                    MMA16(acc[mf][nf], a[mf], b[nf]);
        }
        if (++s_comp == NST) s_comp = 0;
        __syncthreads();
    }
}

// node value GEMMs, both weight slices in one launch
__global__ __launch_bounds__(256, 2) void k_mma_bf16_dual(
    const __nv_bfloat16* __restrict__ A,
    const __nv_bfloat16* __restrict__ Bt1, const __nv_bfloat16* __restrict__ Bt2,
    __nv_bfloat16* __restrict__ C1, __nv_bfloat16* __restrict__ C2,
    int M, int K, int lda)
{
    __shared__ uint32_t sA[NST][BM * 16];
    __shared__ uint32_t sB[NST][BN2 * 16];
    const int half = AEMB / BN2;   // 10
    const __nv_bfloat16* Bt = (blockIdx.x < half) ? Bt1 : Bt2;
    __nv_bfloat16* C = (blockIdx.x < half) ? C1 : C2;

    MmaCtx cx;
    cx.tid = threadIdx.x;
    cx.bm = blockIdx.y * BM;
    cx.bn = (blockIdx.x % half) * BN2;
    int w = cx.tid >> 5, lane = cx.tid & 31;
    cx.wm = (w >> 1) * 32; cx.wn = (w & 1) * 64;
    cx.g = lane >> 2; cx.t = lane & 3;

    float acc[2][8][4];
#pragma unroll
    for (int mf = 0; mf < 2; mf++)
#pragma unroll
        for (int nf = 0; nf < 8; nf++)
#pragma unroll
            for (int q = 0; q < 4; q++) acc[mf][nf][q] = 0.f;

    bf16_mainloop(A, Bt, M, K, lda, cx, sA, sB, acc);

#pragma unroll
    for (int mf = 0; mf < 2; mf++) {
        int r0 = cx.bm + cx.wm + mf * 16 + cx.g, r1 = r0 + 8;
#pragma unroll
        for (int nf = 0; nf < 8; nf++) {
            int cn = cx.bn + cx.wn + nf * 8 + cx.t * 2;
            if (r0 < M) {
                __nv_bfloat162 v;
                v.x = __float2bfloat16(acc[mf][nf][0]);
                v.y = __float2bfloat16(acc[mf][nf][1]);
                *reinterpret_cast<__nv_bfloat162*>(C + (size_t)r0 * AEMB + cn) = v;
            }
            if (r1 < M) {
                __nv_bfloat162 v;
                v.x = __float2bfloat16(acc[mf][nf][2]);
                v.y = __float2bfloat16(acc[mf][nf][3]);
                *reinterpret_cast<__nv_bfloat162*>(C + (size_t)r1 * AEMB + cn) = v;
            }
        }
    }
}

// fused edge value GEMM + gelu + att-weighted pooling
__global__ __launch_bounds__(256, 2) void k_mma_edge_pool(
    const __nv_bfloat16* __restrict__ A, const __nv_bfloat16* __restrict__ Bt,
    const float* __restrict__ b_node, const float* __restrict__ att,
    int M, int K, int lda)
{
    __shared__ uint32_t sA[NST][BM * 16];
    __shared__ uint32_t sB[NST][BN2 * 16];
    MmaCtx cx;
    cx.tid = threadIdx.x;
    cx.bm = blockIdx.y * BM; cx.bn = blockIdx.x * BN2;
    int w = cx.tid >> 5, lane = cx.tid & 31;
    cx.wm = (w >> 1) * 32; cx.wn = (w & 1) * 64;
    cx.g = lane >> 2; cx.t = lane & 3;

    float acc[2][8][4];
#pragma unroll
    for (int mf = 0; mf < 2; mf++)
#pragma unroll
        for (int nf = 0; nf < 8; nf++)
#pragma unroll
            for (int q = 0; q < 4; q++) acc[mf][nf][q] = 0.f;

    bf16_mainloop(A, Bt, M, K, lda, cx, sA, sB, acc);

    const int head = (cx.bn + cx.wn) >> 6;
    float colsum[16];
#pragma unroll
    for (int q = 0; q < 16; q++) colsum[q] = 0.f;

#pragma unroll
    for (int mf = 0; mf < 2; mf++) {
#pragma unroll
        for (int rr = 0; rr < 2; rr++) {
            int e = cx.bm + cx.wm + mf * 16 + cx.g + rr * 8;
            if (e < M) {
                int i = g_src[e], j = g_dst[e];
                float wv = __ldg(att + (size_t)e * NH + head);
                const __nv_bfloat162* P1 =
                    reinterpret_cast<const __nv_bfloat162*>(g_G1b + (size_t)i * AEMB);
                const __nv_bfloat162* P2 =
                    reinterpret_cast<const __nv_bfloat162*>(g_G2b + (size_t)j * AEMB);
#pragma unroll
                for (int nf = 0; nf < 8; nf++) {
                    int cn = cx.bn + cx.wn + nf * 8 + cx.t * 2;
                    float2 v1 = __bfloat1622float2(P1[cn >> 1]);
                    float2 v2 = __bfloat1622float2(P2[cn >> 1]);
                    float x = acc[mf][nf][rr * 2]     + v1.x + v2.x + __ldg(b_node + cn);
                    float y = acc[mf][nf][rr * 2 + 1] + v1.y + v2.y + __ldg(b_node + cn + 1);
                    float gx = 0.5f * x * (1.f + erff(x * 0.70710678118654752f));
                    float gy = 0.5f * y * (1.f + erff(y * 0.70710678118654752f));
                    colsum[nf * 2]     += wv * gx;
                    colsum[nf * 2 + 1] += wv * gy;
                }
            }
        }
    }

#pragma unroll
    for (int q = 0; q < 16; q++) {
        colsum[q] += __shfl_down_sync(0xffffffffu, colsum[q], 16);
        colsum[q] += __shfl_down_sync(0xffffffffu, colsum[q], 8);
        colsum[q] += __shfl_down_sync(0xffffffffu, colsum[q], 4);
    }
    if (lane < 4) {
#pragma unroll
        for (int nf = 0; nf < 8; nf++) {
            int cn = cx.bn + cx.wn + nf * 8 + cx.t * 2;
            atomicAdd(&g_gf[cn],     colsum[nf * 2]);
            atomicAdd(&g_gf[cn + 1], colsum[nf * 2 + 1]);
        }
    }
}

// ---------------- attention logits + softmax ----------------
__global__ void k_logits(const float* __restrict__ b_att) {
    int e = blockIdx.x * blockDim.x + threadIdx.x;
    if (e >= NEDGES) return;
    int i = g_src[e], j = g_dst[e];
    const float* p1 = g_a1 + (size_t)i * 64;
    const float* p2 = g_a2 + (size_t)j * 64;
    const float* pe = g_ae + (size_t)e * 64;
    float* pw = g_w + (size_t)e * NH;
#pragma unroll
    for (int h = 0; h < NH; h++) {
        float v = p1[h] + pe[h] + p2[h] + b_att[h];
        v = v > 0.f ? v : 0.f;
        pw[h] = v * 0.125f;
    }
}

__global__ void k_softmax_stats() {
    int h = blockIdx.x, t = threadIdx.x;
    __shared__ float sm[256];
    float m = -1e30f;
    for (int e = t; e < NEDGES; e += 256) m = fmaxf(m, g_w[(size_t)e * NH + h]);
    sm[t] = m; __syncthreads();
    for (int s = 128; s > 0; s >>= 1) { if (t < s) sm[t] = fmaxf(sm[t], sm[t + s]); __syncthreads(); }
    float mm = sm[0]; __syncthreads();
    float s = 0.f;
    for (int e = t; e < NEDGES; e += 256) s += expf(g_w[(size_t)e * NH + h] - mm);
    sm[t] = s; __syncthreads();
    for (int st = 128; st > 0; st >>= 1) { if (t < st) sm[t] += sm[t + st]; __syncthreads(); }
    if (t == 0) { g_smax[h] = mm; g_sden[h] = sm[0]; }
}

__global__ void k_att_write(float* __restrict__ att_out) {
    int t = blockIdx.x * blockDim.x + threadIdx.x;
    if (t >= NEDGES * NH) return;
    int h = t % NH;
    att_out[t] = expf(g_w[t] - g_smax[h]) / g_sden[h];
}

__global__ void k_zero_gf() {
    int t = blockIdx.x * blockDim.x + threadIdx.x;
    if (t < AEMB) g_gf[t] = 0.f;
}

// ---------------- FFN head ----------------
__global__ void k_ffn1(const float* __restrict__ W1, const float* __restrict__ b1) {
    int n = blockIdx.x * blockDim.x + threadIdx.x;
    if (n >= FF) return;
    float acc = 0.f;
#pragma unroll 4
    for (int k = 0; k < AEMB; k++) acc += g_gf[k] * __ldg(W1 + (size_t)k * FF + n);
    float v = acc + b1[n];
    g_y1[n] = v > 0.f ? v : 0.f;
}

__global__ void k_ffn2(const float* __restrict__ W2, const float* __restrict__ b2) {
    int n = blockIdx.x * blockDim.x + threadIdx.x;
    if (n >= AEMB) return;
    float acc = 0.f;
#pragma unroll 4
    for (int k = 0; k < FF; k++) acc += g_y1[k] * __ldg(W2 + (size_t)k * AEMB + n);
    g_y2[n] = acc + b2[n];
}

__global__ void k_ffn3(const float* __restrict__ Wh, float* __restrict__ out_gf) {
    int n = blockIdx.x * blockDim.x + threadIdx.x;
    if (n >= AEMB) return;
    float acc = 0.f;
#pragma unroll 4
    for (int k = 0; k < AEMB; k++) acc += g_y2[k] * __ldg(Wh + (size_t)k * AEMB + n);
    out_gf[n] = acc;
}

// ---------------- launch ----------------
extern "C" void kernel_launch(void* const* d_in, const int* in_sizes, int n_in,
                              void* d_out, int out_size)
{
    const float* h      = (const float*)d_in[0];
    const float* ec     = (const float*)d_in[1];
    const int*   idxraw = (const int*)  d_in[2];
    const float* W_att  = (const float*)d_in[3];
    const float* b_att  = (const float*)d_in[4];
    const float* W_node = (const float*)d_in[5];
    const float* b_node = (const float*)d_in[6];
    const float* W1     = (const float*)d_in[7];
    const float* b1     = (const float*)d_in[8];
    const float* W2     = (const float*)d_in[9];
    const float* b2     = (const float*)d_in[10];
    const float* Wh     = (const float*)d_in[11];

    float* out     = (float*)d_out;
    float* out_h   = out;
    float* out_ec  = out + (size_t)NNODES * DNODE;
    float* out_gf  = out_ec + (size_t)NEDGES * DEDGE;
    float* out_att = out_gf + AEMB;

    float *pa1, *pa2, *pae, *pWap1, *pWap2, *pWape, *pecp;
    __nv_bfloat16 *pG1b, *pG2b, *phb, *pecb, *pWt1, *pWt2, *pWte;
    cudaGetSymbolAddress((void**)&pa1,  g_a1);
    cudaGetSymbolAddress((void**)&pa2,  g_a2);
    cudaGetSymbolAddress((void**)&pae,  g_ae);
    cudaGetSymbolAddress((void**)&pWap1, g_Wap1);
    cudaGetSymbolAddress((void**)&pWap2, g_Wap2);
    cudaGetSymbolAddress((void**)&pWape, g_Wape);
    cudaGetSymbolAddress((void**)&pecp, g_ecp);
    cudaGetSymbolAddress((void**)&pG1b, g_G1b);
    cudaGetSymbolAddress((void**)&pG2b, g_G2b);
    cudaGetSymbolAddress((void**)&phb,  g_hb);
    cudaGetSymbolAddress((void**)&pecb, g_ecb);
    cudaGetSymbolAddress((void**)&pWt1, g_Wt1);
    cudaGetSymbolAddress((void**)&pWt2, g_Wt2);
    cudaGetSymbolAddress((void**)&pWte, g_Wte);

    // passthrough outputs
    cudaMemcpyAsync(out_h,  h,  (size_t)NNODES * DNODE * sizeof(float), cudaMemcpyDeviceToDevice, 0);
    cudaMemcpyAsync(out_ec, ec, (size_t)NEDGES * DEDGE * sizeof(float), cudaMemcpyDeviceToDevice, 0);

    // indices + conversions
    k_idx_mode<<<1, 32>>>(idxraw);
    k_cvt_idx<<<(NEDGES + 255) / 256, 256>>>(idxraw);
    k_ec2bf<<<(NEDGES * (DEDGE_PAD / 2) + 255) / 256, 256>>>(ec);
    k_h2bf<<<(NNODES * DNODE / 4 + 255) / 256, 256>>>(h);
    {
        dim3 blk(32, 8);
        k_wt<<<dim3(DNODE / 32, AEMB / 32), blk>>>(W_node,                                  pWt1, DNODE, DNODE);
        k_wt<<<dim3(DNODE / 32, AEMB / 32), blk>>>(W_node + (size_t)(DNODE + DEDGE) * AEMB, pWt2, DNODE, DNODE);
        k_wt<<<dim3(DEDGE_PAD / 32, AEMB / 32), blk>>>(W_node + (size_t)DNODE * AEMB,       pWte, DEDGE, DEDGE_PAD);
        k_wap<<<(DNODE * 64 + 255) / 256, 256>>>(W_att);
    }

    // attention logits via tf32 MMA: merged node launch + padded-fp32 edge launch
    k_mma_tf32d<<<dim3(2, (NNODES + BM - 1) / BM), 256>>>(
        h, pWap1, pWap2, pa1, pa2, NNODES, DNODE, DNODE);
    k_mma_tf32s<<<dim3(1, (NEDGES + BM - 1) / BM), 256>>>(
        pecp, pWape, pae, NEDGES, DEDGE_PAD, DEDGE_PAD);

    k_logits<<<(NEDGES + 255) / 256, 256>>>(b_att);
    k_softmax_stats<<<NH, 256>>>();
    k_att_write<<<(NEDGES * NH + 255) / 256, 256>>>(out_att);

    // node value GEMMs, single merged launch (G1b, G2b for fused edge kernel)
    k_zero_gf<<<(AEMB + 255) / 256, 256>>>();
    k_mma_bf16_dual<<<dim3(2 * (AEMB / BN2), (NNODES + BM - 1) / BM), 256>>>(
        phb, pWt1, pWt2, pG1b, pG2b, NNODES, DNODE, DNODE);

    // fused edge value GEMM + gelu + pooling (no Ge intermediate)
    k_mma_edge_pool<<<dim3(AEMB / BN2, (NEDGES + BM - 1) / BM), 256>>>(
        pecb, pWte, b_node, out_att, NEDGES, DEDGE_PAD, DEDGE_PAD);

    // FFN head
    k_ffn1<<<(FF + 255) / 256, 256>>>(W1, b1);
    k_ffn2<<<(AEMB + 255) / 256, 256>>>(W2, b2);
    k_ffn3<<<(AEMB + 255) / 256, 256>>>(Wh, out_gf);
}

// round 15
// speedup vs baseline: 1.0438x; 1.0438x over previous
#include <cuda_runtime.h>
#include <cuda_bf16.h>
#include <math.h>
#include <stdint.h>

#define NNODES 20000
#define NEDGES 100000
#define DNODE 1280
#define DEDGE 505
#define DEDGE_PAD 512
#define NH 20
#define AEMB 1280
#define FF 5120

// ---------------- static device scratch ----------------
__device__ __nv_bfloat16 g_G1b[(size_t)NNODES * AEMB];
__device__ __nv_bfloat16 g_G2b[(size_t)NNODES * AEMB];
__device__ __nv_bfloat16 g_hb [(size_t)NNODES * DNODE];
__device__ __nv_bfloat16 g_ecb[(size_t)NEDGES * DEDGE_PAD];
__device__ float g_ecp[(size_t)NEDGES * DEDGE_PAD];   // fp32 padded (16B-aligned rows)
__device__ __nv_bfloat16 g_Wt1[(size_t)AEMB * DNODE];
__device__ __nv_bfloat16 g_Wt2[(size_t)AEMB * DNODE];
__device__ __nv_bfloat16 g_Wte[(size_t)AEMB * DEDGE_PAD];
__device__ float g_Wap1[DNODE * 64];
__device__ float g_Wap2[DNODE * 64];
__device__ float g_Wape[DEDGE_PAD * 64];
__device__ float g_a1[(size_t)NNODES * 64];
__device__ float g_a2[(size_t)NNODES * 64];
__device__ float g_ae[(size_t)NEDGES * 64];
__device__ float g_w [NEDGES * NH];
__device__ float g_gf[AEMB];
__device__ float g_y1[FF];
__device__ float g_y2[AEMB];
__device__ float g_smax[NH];
__device__ float g_sden[NH];
__device__ int   g_src[NEDGES];
__device__ int   g_dst[NEDGES];
__device__ int   g_idx64;

// ---------------- index dtype sniffing ----------------
__global__ void k_idx_mode(const int* __restrict__ raw) {
    if (blockIdx.x == 0 && threadIdx.x == 0) {
        int is64 = 1;
        for (int s = 0; s < 64; s++)
            if (raw[2 * s + 1] != 0) { is64 = 0; break; }
        g_idx64 = is64;
    }
}

__global__ void k_cvt_idx(const int* __restrict__ raw) {
    int e = blockIdx.x * blockDim.x + threadIdx.x;
    if (e >= NEDGES) return;
    if (g_idx64) { g_src[e] = raw[2 * e]; g_dst[e] = raw[2 * (NEDGES + e)]; }
    else         { g_src[e] = raw[e];     g_dst[e] = raw[NEDGES + e]; }
}

// ---------------- conversions / padding (fused with passthrough copies) ----------
// edge_core -> out_ec (fp32 passthrough) + bf16 padded + fp32 padded, one read
__global__ __launch_bounds__(256) void k_ec2bf(const float* __restrict__ ec,
                                               float* __restrict__ out_ec) {
    int t = blockIdx.x * blockDim.x + threadIdx.x;   // pair index
    if (t >= NEDGES * (DEDGE_PAD / 2)) return;
    int e = t >> 8, p = t & 255;
    int c = p * 2;
    const float* row = ec + (size_t)e * DEDGE;
    float x = (c     < DEDGE) ? row[c]     : 0.f;
    float y = (c + 1 < DEDGE) ? row[c + 1] : 0.f;
    __nv_bfloat162 v; v.x = __float2bfloat16(x); v.y = __float2bfloat16(y);
    *reinterpret_cast<__nv_bfloat162*>(g_ecb + (size_t)e * DEDGE_PAD + c) = v;
    *reinterpret_cast<float2*>(g_ecp + (size_t)e * DEDGE_PAD + c) = make_float2(x, y);
    float* orow = out_ec + (size_t)e * DEDGE;
    if (c < DEDGE)     orow[c] = x;
    if (c + 1 < DEDGE) orow[c + 1] = y;
}

// h -> out_h (fp32 passthrough) + bf16, one read
__global__ __launch_bounds__(256) void k_h2bf(const float* __restrict__ h,
                                              float* __restrict__ out_h) {
    int t = blockIdx.x * blockDim.x + threadIdx.x;   // float4 index
    if (t >= NNODES * DNODE / 4) return;
    float4 v = reinterpret_cast<const float4*>(h)[t];
    reinterpret_cast<float4*>(out_h)[t] = v;
    __nv_bfloat162 a, b;
    a.x = __float2bfloat16(v.x); a.y = __float2bfloat16(v.y);
    b.x = __float2bfloat16(v.z); b.y = __float2bfloat16(v.w);
    __nv_bfloat162* dst = reinterpret_cast<__nv_bfloat162*>(g_hb) + t * 2;
    dst[0] = a; dst[1] = b;
}

// transpose+convert W_node slice -> Wt[1280][Kpad] bf16
__global__ void k_wt(const float* __restrict__ W, __nv_bfloat16* __restrict__ Wt,
                     int Ksrc, int Kpad) {
    __shared__ float tile[32][33];
    int kb = blockIdx.x * 32, nb = blockIdx.y * 32;
    int tx = threadIdx.x, ty = threadIdx.y;   // 32 x 8
    for (int r = ty; r < 32; r += 8) {
        int k = kb + r;
        tile[r][tx] = (k < Ksrc) ? W[(size_t)k * AEMB + nb + tx] : 0.f;
    }
    __syncthreads();
    for (int r = ty; r < 32; r += 8) {
        int n = nb + r, k = kb + tx;
        if (k < Kpad) Wt[(size_t)n * Kpad + k] = __float2bfloat16(tile[tx][r]);
    }
}

// pack W_att slices into zero-padded [K][64] fp32 buffers
__global__ void k_wap(const float* __restrict__ W_att) {
    int t = blockIdx.x * blockDim.x + threadIdx.x;
    if (t >= DNODE * 64) return;
    int k = t >> 6, hh = t & 63;
    g_Wap1[t] = (hh < NH) ? W_att[(size_t)k * NH + hh] : 0.f;
    g_Wap2[t] = (hh < NH) ? W_att[(size_t)(DNODE + DEDGE + k) * NH + hh] : 0.f;
    if (k < DEDGE_PAD)
        g_Wape[t] = (hh < NH && k < DEDGE) ? W_att[(size_t)(DNODE + k) * NH + hh] : 0.f;
}

// ---------------- shared low-level helpers ----------------
__device__ __forceinline__ void cp16(unsigned dst, const void* src, int valid) {
    asm volatile("cp.async.cg.shared.global [%0], [%1], 16, %2;"
                 :: "r"(dst), "l"(src), "r"(valid));
}
__device__ __forceinline__ unsigned f2tf(float x) {
    unsigned u; asm("cvt.rna.tf32.f32 %0, %1;" : "=r"(u) : "f"(x)); return u;
}

// ---------------- tf32 tensor-core GEMM body (att logits): C[M,64] = A @ B ------
#define BM 128
#define BN 64
#define BK 32

#define MMA8(d, a, b) asm volatile( \
    "mma.sync.aligned.m16n8k8.row.col.f32.tf32.tf32.f32 " \
    "{%0,%1,%2,%3}, {%4,%5,%6,%7}, {%8,%9}, {%0,%1,%2,%3};" \
    : "+f"(d[0]), "+f"(d[1]), "+f"(d[2]), "+f"(d[3]) \
    : "r"(a[0]), "r"(a[1]), "r"(a[2]), "r"(a[3]), "r"(b[0]), "r"(b[1]))

__device__ __forceinline__ void tf32_body(
    const float* __restrict__ A, const float* __restrict__ B, float* __restrict__ C,
    int M, int K, int lda, int bm)
{
    __shared__ float sA[2][BM * BK];
    __shared__ float sB[2][BK * BN];

    const int tid = threadIdx.x;
    const int w = tid >> 5, lane = tid & 31;
    const int wm = (w >> 1) * 32;
    const int wn = (w & 1) * 32;
    const int g = lane >> 2, t = lane & 3;

    float acc[2][4][4];
#pragma unroll
    for (int mf = 0; mf < 2; mf++)
#pragma unroll
        for (int nf = 0; nf < 4; nf++)
#pragma unroll
            for (int q = 0; q < 4; q++) acc[mf][nf][q] = 0.f;

    const int nK = (K + BK - 1) / BK;

    auto loadA = [&](int kt, int s) {
#pragma unroll
        for (int p = 0; p < 4; p++) {
            int m  = (tid >> 3) + p * 32;
            int k4 = (tid & 7) * 4;
            int gm = bm + m;
            int gk = kt * BK + k4;
            int chunk = m * BK + (k4 ^ ((m & 7) << 2));
            int rem = K - gk;
            int valid = (gm < M) ? (rem >= 4 ? 16 : (rem > 0 ? rem * 4 : 0)) : 0;
            const float* src = (valid > 0) ? (A + (size_t)gm * lda + gk) : A;
            cp16((unsigned)__cvta_generic_to_shared(&sA[s][chunk]), src, valid);
        }
    };
    auto loadB = [&](int kt, int s) {
#pragma unroll
        for (int p = 0; p < 2; p++) {
            int k  = (tid >> 4) + p * 16;
            int n4 = (tid & 15) * 4;
            int gk = kt * BK + k;
            int valid = (gk < K) ? 16 : 0;
            const float* src = (valid > 0) ? (B + (size_t)gk * 64 + n4) : B;
            unsigned dst = (unsigned)__cvta_generic_to_shared(
                &sB[s][k * BN + (n4 ^ ((k & 3) << 3))]);
            cp16(dst, src, valid);
        }
    };

    loadA(0, 0); loadB(0, 0);
    asm volatile("cp.async.commit_group;");

    for (int kt = 0; kt < nK; kt++) {
        int cur = kt & 1, nxt = cur ^ 1;
        if (kt + 1 < nK) {
            loadA(kt + 1, nxt); loadB(kt + 1, nxt);
            asm volatile("cp.async.commit_group;");
            asm volatile("cp.async.wait_group 1;");
        } else {
            asm volatile("cp.async.wait_group 0;");
        }
        __syncthreads();

#pragma unroll
        for (int ks = 0; ks < 4; ks++) {
            unsigned a[2][4], b[4][2];
            int c0 = ks * 8 + t, c1 = c0 + 4;
#pragma unroll
            for (int mf = 0; mf < 2; mf++) {
                int r0 = wm + mf * 16 + g, r1 = r0 + 8;
                int s0 = (r0 & 7) << 2, s1 = (r1 & 7) << 2;
                a[mf][0] = f2tf(sA[cur][r0 * BK + (c0 ^ s0)]);
                a[mf][1] = f2tf(sA[cur][r1 * BK + (c0 ^ s1)]);
                a[mf][2] = f2tf(sA[cur][r0 * BK + (c1 ^ s0)]);
                a[mf][3] = f2tf(sA[cur][r1 * BK + (c1 ^ s1)]);
            }
            int kr0 = ks * 8 + t, kr1 = kr0 + 4;
            int sw = (t & 3) << 3;
#pragma unroll
            for (int nf = 0; nf < 4; nf++) {
                int n = wn + nf * 8 + g;
                b[nf][0] = f2tf(sB[cur][kr0 * BN + (n ^ sw)]);
                b[nf][1] = f2tf(sB[cur][kr1 * BN + (n ^ sw)]);
            }
#pragma unroll
            for (int mf = 0; mf < 2; mf++)
#pragma unroll
                for (int nf = 0; nf < 4; nf++)
                    MMA8(acc[mf][nf], a[mf], b[nf]);
        }
        __syncthreads();
    }

#pragma unroll
    for (int mf = 0; mf < 2; mf++) {
        int r0 = bm + wm + mf * 16 + g, r1 = r0 + 8;
#pragma unroll
        for (int nf = 0; nf < 4; nf++) {
            int cn = wn + nf * 8 + t * 2;
            if (r0 < M) {
                float2 v = make_float2(acc[mf][nf][0], acc[mf][nf][1]);
                *reinterpret_cast<float2*>(C + (size_t)r0 * 64 + cn) = v;
            }
            if (r1 < M) {
                float2 v = make_float2(acc[mf][nf][2], acc[mf][nf][3]);
                *reinterpret_cast<float2*>(C + (size_t)r1 * 64 + cn) = v;
            }
        }
    }
}

// single-matrix variant (edge att logits)
__global__ __launch_bounds__(256, 2) void k_mma_tf32s(
    const float* __restrict__ A, const float* __restrict__ B, float* __restrict__ C,
    int M, int K, int lda)
{
    tf32_body(A, B, C, M, K, lda, blockIdx.y * BM);
}

// dual variant: both node att-logit GEMMs in one launch (shared A = h)
__global__ __launch_bounds__(256, 2) void k_mma_tf32d(
    const float* __restrict__ A,
    const float* __restrict__ B1, const float* __restrict__ B2,
    float* __restrict__ C1, float* __restrict__ C2,
    int M, int K, int lda)
{
    const float* B = (blockIdx.x == 0) ? B1 : B2;
    float* C = (blockIdx.x == 0) ? C1 : C2;
    tf32_body(A, B, C, M, K, lda, blockIdx.y * BM);
}

// ---------------- bf16 tensor-core GEMM core (scalar-LDS fragments, 3-stage) -----
#define BN2 128
#define BKB 32
#define NST 3

#define MMA16(d, a, b) asm volatile( \
    "mma.sync.aligned.m16n8k16.row.col.f32.bf16.bf16.f32 " \
    "{%0,%1,%2,%3}, {%4,%5,%6,%7}, {%8,%9}, {%0,%1,%2,%3};" \
    : "+f"(d[0]), "+f"(d[1]), "+f"(d[2]), "+f"(d[3]) \
    : "r"(a[0]), "r"(a[1]), "r"(a[2]), "r"(a[3]), "r"(b[0]), "r"(b[1]))

struct MmaCtx {
    int tid, bm, bn, wm, wn, g, t;
};

__device__ __forceinline__ void bf16_mainloop(
    const __nv_bfloat16* __restrict__ A, const __nv_bfloat16* __restrict__ Bt,
    int M, int K, int lda, const MmaCtx& cx,
    uint32_t (*sA)[BM * 16], uint32_t (*sB)[BN2 * 16],
    float acc[2][8][4])
{
    const int tid = cx.tid, bm = cx.bm, bn = cx.bn;
    const int wm = cx.wm, wn = cx.wn, g = cx.g, t = cx.t;

    const int nK = K / BKB;

    auto loadA = [&](int kt, int s) {
#pragma unroll
        for (int p = 0; p < 2; p++) {
            int idx = tid + p * 256;
            int m = idx >> 2, c4 = idx & 3;
            int gm = bm + m;
            int valid = (gm < M) ? 16 : 0;
            const __nv_bfloat16* src = (valid > 0)
                ? (A + (size_t)gm * lda + kt * BKB + c4 * 8) : A;
            unsigned dst = (unsigned)__cvta_generic_to_shared(
                &sA[s][m * 16 + (c4 ^ ((m >> 1) & 3)) * 4]);
            cp16(dst, src, valid);
        }
    };
    auto loadB = [&](int kt, int s) {
#pragma unroll
        for (int p = 0; p < 2; p++) {
            int idx = tid + p * 256;
            int n = idx >> 2, c4 = idx & 3;
            const __nv_bfloat16* src = Bt + (size_t)(bn + n) * K + kt * BKB + c4 * 8;
            unsigned dst = (unsigned)__cvta_generic_to_shared(
                &sB[s][n * 16 + (c4 ^ ((n >> 1) & 3)) * 4]);
            cp16(dst, src, 16);
        }
    };

    loadA(0, 0); loadB(0, 0);
    asm volatile("cp.async.commit_group;");
    if (1 < nK) {
        loadA(1, 1); loadB(1, 1);
        asm volatile("cp.async.commit_group;");
    }

    int s_comp = 0, s_load = 2;

    for (int kt = 0; kt < nK; kt++) {
        if (kt == nK - 1) { asm volatile("cp.async.wait_group 0;"); }
        else              { asm volatile("cp.async.wait_group 1;"); }
        __syncthreads();

        if (kt + 2 < nK) {
            loadA(kt + 2, s_load); loadB(kt + 2, s_load);
            asm volatile("cp.async.commit_group;");
            if (++s_load == NST) s_load = 0;
        }

        int cur = s_comp;
#pragma unroll
        for (int ks = 0; ks < 2; ks++) {
            uint32_t a[2][4], b[8][2];
            int w0 = t + ks * 8, w1 = t + 4 + ks * 8;
#pragma unroll
            for (int mf = 0; mf < 2; mf++) {
                int r0 = wm + mf * 16 + g, r1 = r0 + 8;
                int s0 = ((r0 >> 1) & 3) << 2;
                a[mf][0] = sA[cur][r0 * 16 + (w0 ^ s0)];
                a[mf][1] = sA[cur][r1 * 16 + (w0 ^ s0)];
                a[mf][2] = sA[cur][r0 * 16 + (w1 ^ s0)];
                a[mf][3] = sA[cur][r1 * 16 + (w1 ^ s0)];
            }
#pragma unroll
            for (int nf = 0; nf < 8; nf++) {
                int n0 = wn + nf * 8 + g;
                int sn = ((n0 >> 1) & 3) << 2;
                b[nf][0] = sB[cur][n0 * 16 + (w0 ^ sn)];
                b[nf][1] = sB[cur][n0 * 16 + (w1 ^ sn)];
            }
#pragma unroll
            for (int mf = 0; mf < 2; mf++)
#pragma unroll
                for (int nf = 0; nf < 8; nf++)
                    MMA16(acc[mf][nf], a[mf], b[nf]);
        }
        if (++s_comp == NST) s_comp = 0;
        __syncthreads();
    }
}

// node value GEMMs, both weight slices in one launch
__global__ __launch_bounds__(256, 2) void k_mma_bf16_dual(
    const __nv_bfloat16* __restrict__ A,
    const __nv_bfloat16* __restrict__ Bt1, const __nv_bfloat16* __restrict__ Bt2,
    __nv_bfloat16* __restrict__ C1, __nv_bfloat16* __restrict__ C2,
    int M, int K, int lda)
{
    __shared__ uint32_t sA[NST][BM * 16];
    __shared__ uint32_t sB[NST][BN2 * 16];
    const int half = AEMB / BN2;   // 10
    const __nv_bfloat16* Bt = (blockIdx.x < half) ? Bt1 : Bt2;
    __nv_bfloat16* C = (blockIdx.x < half) ? C1 : C2;

    MmaCtx cx;
    cx.tid = threadIdx.x;
    cx.bm = blockIdx.y * BM;
    cx.bn = (blockIdx.x % half) * BN2;
    int w = cx.tid >> 5, lane = cx.tid & 31;
    cx.wm = (w >> 1) * 32; cx.wn = (w & 1) * 64;
    cx.g = lane >> 2; cx.t = lane & 3;

    float acc[2][8][4];
#pragma unroll
    for (int mf = 0; mf < 2; mf++)
#pragma unroll
        for (int nf = 0; nf < 8; nf++)
#pragma unroll
            for (int q = 0; q < 4; q++) acc[mf][nf][q] = 0.f;

    bf16_mainloop(A, Bt, M, K, lda, cx, sA, sB, acc);

#pragma unroll
    for (int mf = 0; mf < 2; mf++) {
        int r0 = cx.bm + cx.wm + mf * 16 + cx.g, r1 = r0 + 8;
#pragma unroll
        for (int nf = 0; nf < 8; nf++) {
            int cn = cx.bn + cx.wn + nf * 8 + cx.t * 2;
            if (r0 < M) {
                __nv_bfloat162 v;
                v.x = __float2bfloat16(acc[mf][nf][0]);
                v.y = __float2bfloat16(acc[mf][nf][1]);
                *reinterpret_cast<__nv_bfloat162*>(C + (size_t)r0 * AEMB + cn) = v;
            }
            if (r1 < M) {
                __nv_bfloat162 v;
                v.x = __float2bfloat16(acc[mf][nf][2]);
                v.y = __float2bfloat16(acc[mf][nf][3]);
                *reinterpret_cast<__nv_bfloat162*>(C + (size_t)r1 * AEMB + cn) = v;
            }
        }
    }
}

// fused edge value GEMM + gelu + att-weighted pooling
__global__ __launch_bounds__(256, 2) void k_mma_edge_pool(
    const __nv_bfloat16* __restrict__ A, const __nv_bfloat16* __restrict__ Bt,
    const float* __restrict__ b_node, const float* __restrict__ att,
    int M, int K, int lda)
{
    __shared__ uint32_t sA[NST][BM * 16];
    __shared__ uint32_t sB[NST][BN2 * 16];
    MmaCtx cx;
    cx.tid = threadIdx.x;
    cx.bm = blockIdx.y * BM; cx.bn = blockIdx.x * BN2;
    int w = cx.tid >> 5, lane = cx.tid & 31;
    cx.wm = (w >> 1) * 32; cx.wn = (w & 1) * 64;
    cx.g = lane >> 2; cx.t = lane & 3;

    float acc[2][8][4];
#pragma unroll
    for (int mf = 0; mf < 2; mf++)
#pragma unroll
        for (int nf = 0; nf < 8; nf++)
#pragma unroll
            for (int q = 0; q < 4; q++) acc[mf][nf][q] = 0.f;

    bf16_mainloop(A, Bt, M, K, lda, cx, sA, sB, acc);

    const int head = (cx.bn + cx.wn) >> 6;
    float colsum[16];
#pragma unroll
    for (int q = 0; q < 16; q++) colsum[q] = 0.f;

#pragma unroll
    for (int mf = 0; mf < 2; mf++) {
#pragma unroll
        for (int rr = 0; rr < 2; rr++) {
            int e = cx.bm + cx.wm + mf * 16 + cx.g + rr * 8;
            if (e < M) {
                int i = g_src[e], j = g_dst[e];
                float wv = __ldg(att + (size_t)e * NH + head);
                const __nv_bfloat162* P1 =
                    reinterpret_cast<const __nv_bfloat162*>(g_G1b + (size_t)i * AEMB);
                const __nv_bfloat162* P2 =
                    reinterpret_cast<const __nv_bfloat162*>(g_G2b + (size_t)j * AEMB);
#pragma unroll
                for (int nf = 0; nf < 8; nf++) {
                    int cn = cx.bn + cx.wn + nf * 8 + cx.t * 2;
                    float2 v1 = __bfloat1622float2(P1[cn >> 1]);
                    float2 v2 = __bfloat1622float2(P2[cn >> 1]);
                    float x = acc[mf][nf][rr * 2]     + v1.x + v2.x + __ldg(b_node + cn);
                    float y = acc[mf][nf][rr * 2 + 1] + v1.y + v2.y + __ldg(b_node + cn + 1);
                    float gx = 0.5f * x * (1.f + erff(x * 0.70710678118654752f));
                    float gy = 0.5f * y * (1.f + erff(y * 0.70710678118654752f));
                    colsum[nf * 2]     += wv * gx;
                    colsum[nf * 2 + 1] += wv * gy;
                }
            }
        }
    }

#pragma unroll
    for (int q = 0; q < 16; q++) {
        colsum[q] += __shfl_down_sync(0xffffffffu, colsum[q], 16);
        colsum[q] += __shfl_down_sync(0xffffffffu, colsum[q], 8);
        colsum[q] += __shfl_down_sync(0xffffffffu, colsum[q], 4);
    }
    if (lane < 4) {
#pragma unroll
        for (int nf = 0; nf < 8; nf++) {
            int cn = cx.bn + cx.wn + nf * 8 + cx.t * 2;
            atomicAdd(&g_gf[cn],     colsum[nf * 2]);
            atomicAdd(&g_gf[cn + 1], colsum[nf * 2 + 1]);
        }
    }
}

// ---------------- attention logits + softmax ----------------
__global__ void k_logits(const float* __restrict__ b_att) {
    int e = blockIdx.x * blockDim.x + threadIdx.x;
    if (e >= NEDGES) return;
    int i = g_src[e], j = g_dst[e];
    const float* p1 = g_a1 + (size_t)i * 64;
    const float* p2 = g_a2 + (size_t)j * 64;
    const float* pe = g_ae + (size_t)e * 64;
    float* pw = g_w + (size_t)e * NH;
#pragma unroll
    for (int h = 0; h < NH; h++) {
        float v = p1[h] + pe[h] + p2[h] + b_att[h];
        v = v > 0.f ? v : 0.f;
        pw[h] = v * 0.125f;
    }
}

__global__ void k_softmax_stats() {
    int h = blockIdx.x, t = threadIdx.x;
    __shared__ float sm[256];
    float m = -1e30f;
    for (int e = t; e < NEDGES; e += 256) m = fmaxf(m, g_w[(size_t)e * NH + h]);
    sm[t] = m; __syncthreads();
    for (int s = 128; s > 0; s >>= 1) { if (t < s) sm[t] = fmaxf(sm[t], sm[t + s]); __syncthreads(); }
    float mm = sm[0]; __syncthreads();
    float s = 0.f;
    for (int e = t; e < NEDGES; e += 256) s += expf(g_w[(size_t)e * NH + h] - mm);
    sm[t] = s; __syncthreads();
    for (int st = 128; st > 0; st >>= 1) { if (t < st) sm[t] += sm[t + st]; __syncthreads(); }
    if (t == 0) { g_smax[h] = mm; g_sden[h] = sm[0]; }
}

__global__ void k_att_write(float* __restrict__ att_out) {
    int t = blockIdx.x * blockDim.x + threadIdx.x;
    if (t >= NEDGES * NH) return;
    int h = t % NH;
    att_out[t] = expf(g_w[t] - g_smax[h]) / g_sden[h];
}

__global__ void k_zero_gf() {
    int t = blockIdx.x * blockDim.x + threadIdx.x;
    if (t < AEMB) g_gf[t] = 0.f;
}

// ---------------- FFN head ----------------
__global__ void k_ffn1(const float* __restrict__ W1, const float* __restrict__ b1) {
    int n = blockIdx.x * blockDim.x + threadIdx.x;
    if (n >= FF) return;
    float acc = 0.f;
#pragma unroll 4
    for (int k = 0; k < AEMB; k++) acc += g_gf[k] * __ldg(W1 + (size_t)k * FF + n);
    float v = acc + b1[n];
    g_y1[n] = v > 0.f ? v : 0.f;
}

__global__ void k_ffn2(const float* __restrict__ W2, const float* __restrict__ b2) {
    int n = blockIdx.x * blockDim.x + threadIdx.x;
    if (n >= AEMB) return;
    float acc = 0.f;
#pragma unroll 4
    for (int k = 0; k < FF; k++) acc += g_y1[k] * __ldg(W2 + (size_t)k * AEMB + n);
    g_y2[n] = acc + b2[n];
}

__global__ void k_ffn3(const float* __restrict__ Wh, float* __restrict__ out_gf) {
    int n = blockIdx.x * blockDim.x + threadIdx.x;
    if (n >= AEMB) return;
    float acc = 0.f;
#pragma unroll 4
    for (int k = 0; k < AEMB; k++) acc += g_y2[k] * __ldg(Wh + (size_t)k * AEMB + n);
    out_gf[n] = acc;
}

// ---------------- launch ----------------
extern "C" void kernel_launch(void* const* d_in, const int* in_sizes, int n_in,
                              void* d_out, int out_size)
{
    const float* h      = (const float*)d_in[0];
    const float* ec     = (const float*)d_in[1];
    const int*   idxraw = (const int*)  d_in[2];
    const float* W_att  = (const float*)d_in[3];
    const float* b_att  = (const float*)d_in[4];
    const float* W_node = (const float*)d_in[5];
    const float* b_node = (const float*)d_in[6];
    const float* W1     = (const float*)d_in[7];
    const float* b1     = (const float*)d_in[8];
    const float* W2     = (const float*)d_in[9];
    const float* b2     = (const float*)d_in[10];
    const float* Wh     = (const float*)d_in[11];

    float* out     = (float*)d_out;
    float* out_h   = out;
    float* out_ec  = out + (size_t)NNODES * DNODE;
    float* out_gf  = out_ec + (size_t)NEDGES * DEDGE;
    float* out_att = out_gf + AEMB;

    float *pa1, *pa2, *pae, *pWap1, *pWap2, *pWape, *pecp;
    __nv_bfloat16 *pG1b, *pG2b, *phb, *pecb, *pWt1, *pWt2, *pWte;
    cudaGetSymbolAddress((void**)&pa1,  g_a1);
    cudaGetSymbolAddress((void**)&pa2,  g_a2);
    cudaGetSymbolAddress((void**)&pae,  g_ae);
    cudaGetSymbolAddress((void**)&pWap1, g_Wap1);
    cudaGetSymbolAddress((void**)&pWap2, g_Wap2);
    cudaGetSymbolAddress((void**)&pWape, g_Wape);
    cudaGetSymbolAddress((void**)&pecp, g_ecp);
    cudaGetSymbolAddress((void**)&pG1b, g_G1b);
    cudaGetSymbolAddress((void**)&pG2b, g_G2b);
    cudaGetSymbolAddress((void**)&phb,  g_hb);
    cudaGetSymbolAddress((void**)&pecb, g_ecb);
    cudaGetSymbolAddress((void**)&pWt1, g_Wt1);
    cudaGetSymbolAddress((void**)&pWt2, g_Wt2);
    cudaGetSymbolAddress((void**)&pWte, g_Wte);

    // ---- stream ops 0..4: node-GEMM prerequisites (h passthrough fused) ----
    k_h2bf<<<(NNODES * DNODE / 4 + 255) / 256, 256>>>(h, out_h);               // 0
    {
        dim3 blk(32, 8);
        k_wt<<<dim3(DNODE / 32, AEMB / 32), blk>>>(W_node, pWt1, DNODE, DNODE);                                   // 1
        k_wt<<<dim3(DNODE / 32, AEMB / 32), blk>>>(W_node + (size_t)(DNODE + DEDGE) * AEMB, pWt2, DNODE, DNODE);  // 2
        k_wt<<<dim3(DEDGE_PAD / 32, AEMB / 32), blk>>>(W_node + (size_t)DNODE * AEMB, pWte, DEDGE, DEDGE_PAD);    // 3
    }
    k_zero_gf<<<(AEMB + 255) / 256, 256>>>();                                  // 4

    // ---- stream op 5: the dominant kernel (ncu -s 5 -c 1 captures this) ----
    k_mma_bf16_dual<<<dim3(2 * (AEMB / BN2), (NNODES + BM - 1) / BM), 256>>>(
        phb, pWt1, pWt2, pG1b, pG2b, NNODES, DNODE, DNODE);                    // 5

    // ---- remaining prep (edge passthrough fused into ec2bf) ----
    k_idx_mode<<<1, 32>>>(idxraw);
    k_cvt_idx<<<(NEDGES + 255) / 256, 256>>>(idxraw);
    k_ec2bf<<<(NEDGES * (DEDGE_PAD / 2) + 255) / 256, 256>>>(ec, out_ec);
    k_wap<<<(DNODE * 64 + 255) / 256, 256>>>(W_att);

    // attention logits via tf32 MMA, then softmax
    k_mma_tf32d<<<dim3(2, (NNODES + BM - 1) / BM), 256>>>(
        h, pWap1, pWap2, pa1, pa2, NNODES, DNODE, DNODE);
    k_mma_tf32s<<<dim3(1, (NEDGES + BM - 1) / BM), 256>>>(
        pecp, pWape, pae, NEDGES, DEDGE_PAD, DEDGE_PAD);

    k_logits<<<(NEDGES + 255) / 256, 256>>>(b_att);
    k_softmax_stats<<<NH, 256>>>();
    k_att_write<<<(NEDGES * NH + 255) / 256, 256>>>(out_att);

    // fused edge value GEMM + gelu + pooling (needs G1b/G2b, att, ecb)
    k_mma_edge_pool<<<dim3(AEMB / BN2, (NEDGES + BM - 1) / BM), 256>>>(
        pecb, pWte, b_node, out_att, NEDGES, DEDGE_PAD, DEDGE_PAD);

    // FFN head
    k_ffn1<<<(FF + 255) / 256, 256>>>(W1, b1);
    k_ffn2<<<(AEMB + 255) / 256, 256>>>(W2, b2);
    k_ffn3<<<(AEMB + 255) / 256, 256>>>(Wh, out_gf);
}

// round 16
// speedup vs baseline: 1.0476x; 1.0037x over previous
#include <cuda_runtime.h>
#include <cuda_bf16.h>
#include <math.h>
#include <stdint.h>

#define NNODES 20000
#define NEDGES 100000
#define DNODE 1280
#define DEDGE 505
#define DEDGE_PAD 512
#define NH 20
#define AEMB 1280
#define FF 5120

// ---------------- static device scratch ----------------
__device__ __nv_bfloat16 g_G1b[(size_t)NNODES * AEMB];
__device__ __nv_bfloat16 g_G2b[(size_t)NNODES * AEMB];
__device__ __nv_bfloat16 g_hb [(size_t)NNODES * DNODE];
__device__ __nv_bfloat16 g_ecb[(size_t)NEDGES * DEDGE_PAD];
__device__ __nv_bfloat16 g_Wt1[(size_t)AEMB * DNODE];
__device__ __nv_bfloat16 g_Wt2[(size_t)AEMB * DNODE];
__device__ __nv_bfloat16 g_Wte[(size_t)AEMB * DEDGE_PAD];
__device__ float g_Wap1[DNODE * 64];
__device__ float g_Wap2[DNODE * 64];
__device__ float g_Wape[DEDGE_PAD * 64];
__device__ float g_a1[(size_t)NNODES * 64];
__device__ float g_a2[(size_t)NNODES * 64];
__device__ float g_ae[(size_t)NEDGES * 64];
__device__ float g_w [NEDGES * NH];
__device__ float g_gf[AEMB];
__device__ float g_y1[FF];
__device__ float g_y2[AEMB];
__device__ float g_smax[NH];
__device__ float g_sden[NH];
__device__ int   g_src[NEDGES];
__device__ int   g_dst[NEDGES];
__device__ int   g_idx64;

// ---------------- index dtype sniffing ----------------
__global__ void k_idx_mode(const int* __restrict__ raw) {
    if (blockIdx.x == 0 && threadIdx.x == 0) {
        int is64 = 1;
        for (int s = 0; s < 64; s++)
            if (raw[2 * s + 1] != 0) { is64 = 0; break; }
        g_idx64 = is64;
    }
}

__global__ void k_cvt_idx(const int* __restrict__ raw) {
    int e = blockIdx.x * blockDim.x + threadIdx.x;
    if (e >= NEDGES) return;
    if (g_idx64) { g_src[e] = raw[2 * e]; g_dst[e] = raw[2 * (NEDGES + e)]; }
    else         { g_src[e] = raw[e];     g_dst[e] = raw[NEDGES + e]; }
}

// ---------------- conversions / padding ----------------
// h -> out_h (fp32 passthrough) + bf16, one read
__global__ __launch_bounds__(256) void k_h2bf(const float* __restrict__ h,
                                              float* __restrict__ out_h) {
    int t = blockIdx.x * blockDim.x + threadIdx.x;   // float4 index
    if (t >= NNODES * DNODE / 4) return;
    float4 v = reinterpret_cast<const float4*>(h)[t];
    reinterpret_cast<float4*>(out_h)[t] = v;
    __nv_bfloat162 a, b;
    a.x = __float2bfloat16(v.x); a.y = __float2bfloat16(v.y);
    b.x = __float2bfloat16(v.z); b.y = __float2bfloat16(v.w);
    __nv_bfloat162* dst = reinterpret_cast<__nv_bfloat162*>(g_hb) + t * 2;
    dst[0] = a; dst[1] = b;
}

// transpose+convert W_node slice -> Wt[1280][Kpad] bf16
__global__ void k_wt(const float* __restrict__ W, __nv_bfloat16* __restrict__ Wt,
                     int Ksrc, int Kpad) {
    __shared__ float tile[32][33];
    int kb = blockIdx.x * 32, nb = blockIdx.y * 32;
    int tx = threadIdx.x, ty = threadIdx.y;   // 32 x 8
    for (int r = ty; r < 32; r += 8) {
        int k = kb + r;
        tile[r][tx] = (k < Ksrc) ? W[(size_t)k * AEMB + nb + tx] : 0.f;
    }
    __syncthreads();
    for (int r = ty; r < 32; r += 8) {
        int n = nb + r, k = kb + tx;
        if (k < Kpad) Wt[(size_t)n * Kpad + k] = __float2bfloat16(tile[tx][r]);
    }
}

// pack W_att slices into zero-padded [K][64] fp32 buffers
__global__ void k_wap(const float* __restrict__ W_att) {
    int t = blockIdx.x * blockDim.x + threadIdx.x;
    if (t >= DNODE * 64) return;
    int k = t >> 6, hh = t & 63;
    g_Wap1[t] = (hh < NH) ? W_att[(size_t)k * NH + hh] : 0.f;
    g_Wap2[t] = (hh < NH) ? W_att[(size_t)(DNODE + DEDGE + k) * NH + hh] : 0.f;
    if (k < DEDGE_PAD)
        g_Wape[t] = (hh < NH && k < DEDGE) ? W_att[(size_t)(DNODE + k) * NH + hh] : 0.f;
}

__global__ void k_zero_gf() {
    int t = blockIdx.x * blockDim.x + threadIdx.x;
    if (t < AEMB) g_gf[t] = 0.f;
}

// ---------------- shared low-level helpers ----------------
__device__ __forceinline__ void cp16(unsigned dst, const void* src, int valid) {
    asm volatile("cp.async.cg.shared.global [%0], [%1], 16, %2;"
                 :: "r"(dst), "l"(src), "r"(valid));
}
__device__ __forceinline__ void cp4(unsigned dst, const void* src, int valid) {
    asm volatile("cp.async.ca.shared.global [%0], [%1], 4, %2;"
                 :: "r"(dst), "l"(src), "r"(valid));
}
__device__ __forceinline__ unsigned f2tf(float x) {
    unsigned u; asm("cvt.rna.tf32.f32 %0, %1;" : "=r"(u) : "f"(x)); return u;
}

// ---------------- tf32 tensor-core GEMM body (att logits): C[M,64] = A @ B ------
#define BM 128
#define BN 64
#define BK 32

#define MMA8(d, a, b) asm volatile( \
    "mma.sync.aligned.m16n8k8.row.col.f32.tf32.tf32.f32 " \
    "{%0,%1,%2,%3}, {%4,%5,%6,%7}, {%8,%9}, {%0,%1,%2,%3};" \
    : "+f"(d[0]), "+f"(d[1]), "+f"(d[2]), "+f"(d[3]) \
    : "r"(a[0]), "r"(a[1]), "r"(a[2]), "r"(a[3]), "r"(b[0]), "r"(b[1]))

template<bool A16>
__device__ __forceinline__ void tf32_body(
    const float* __restrict__ A, const float* __restrict__ B, float* __restrict__ C,
    int M, int K, int lda, int bm,
    float (*sA)[BM * BK], float (*sB)[BK * BN])
{
    const int tid = threadIdx.x;
    const int w = tid >> 5, lane = tid & 31;
    const int wm = (w >> 1) * 32;
    const int wn = (w & 1) * 32;
    const int g = lane >> 2, t = lane & 3;

    float acc[2][4][4];
#pragma unroll
    for (int mf = 0; mf < 2; mf++)
#pragma unroll
        for (int nf = 0; nf < 4; nf++)
#pragma unroll
            for (int q = 0; q < 4; q++) acc[mf][nf][q] = 0.f;

    const int nK = (K + BK - 1) / BK;

    auto loadA = [&](int kt, int s) {
#pragma unroll
        for (int p = 0; p < 4; p++) {
            int m  = (tid >> 3) + p * 32;
            int k4 = (tid & 7) * 4;
            int gm = bm + m;
            int gk = kt * BK + k4;
            int chunk = m * BK + (k4 ^ ((m & 7) << 2));
            if (A16) {
                int rem = K - gk;
                int valid = (gm < M) ? (rem >= 4 ? 16 : (rem > 0 ? rem * 4 : 0)) : 0;
                const float* src = (valid > 0) ? (A + (size_t)gm * lda + gk) : A;
                cp16((unsigned)__cvta_generic_to_shared(&sA[s][chunk]), src, valid);
            } else {
#pragma unroll
                for (int q = 0; q < 4; q++) {
                    int valid = (gm < M && gk + q < K) ? 4 : 0;
                    const float* src = (valid > 0) ? (A + (size_t)gm * lda + gk + q) : A;
                    cp4((unsigned)__cvta_generic_to_shared(&sA[s][chunk + q]), src, valid);
                }
            }
        }
    };
    auto loadB = [&](int kt, int s) {
#pragma unroll
        for (int p = 0; p < 2; p++) {
            int k  = (tid >> 4) + p * 16;
            int n4 = (tid & 15) * 4;
            int gk = kt * BK + k;
            int valid = (gk < K) ? 16 : 0;
            const float* src = (valid > 0) ? (B + (size_t)gk * 64 + n4) : B;
            unsigned dst = (unsigned)__cvta_generic_to_shared(
                &sB[s][k * BN + (n4 ^ ((k & 3) << 3))]);
            cp16(dst, src, valid);
        }
    };

    loadA(0, 0); loadB(0, 0);
    asm volatile("cp.async.commit_group;");

    for (int kt = 0; kt < nK; kt++) {
        int cur = kt & 1, nxt = cur ^ 1;
        if (kt + 1 < nK) {
            loadA(kt + 1, nxt); loadB(kt + 1, nxt);
            asm volatile("cp.async.commit_group;");
            asm volatile("cp.async.wait_group 1;");
        } else {
            asm volatile("cp.async.wait_group 0;");
        }
        __syncthreads();

#pragma unroll
        for (int ks = 0; ks < 4; ks++) {
            unsigned a[2][4], b[4][2];
            int c0 = ks * 8 + t, c1 = c0 + 4;
#pragma unroll
            for (int mf = 0; mf < 2; mf++) {
                int r0 = wm + mf * 16 + g, r1 = r0 + 8;
                int s0 = (r0 & 7) << 2, s1 = (r1 & 7) << 2;
                a[mf][0] = f2tf(sA[cur][r0 * BK + (c0 ^ s0)]);
                a[mf][1] = f2tf(sA[cur][r1 * BK + (c0 ^ s1)]);
                a[mf][2] = f2tf(sA[cur][r0 * BK + (c1 ^ s0)]);
                a[mf][3] = f2tf(sA[cur][r1 * BK + (c1 ^ s1)]);
            }
            int kr0 = ks * 8 + t, kr1 = kr0 + 4;
            int sw = (t & 3) << 3;
#pragma unroll
            for (int nf = 0; nf < 4; nf++) {
                int n = wn + nf * 8 + g;
                b[nf][0] = f2tf(sB[cur][kr0 * BN + (n ^ sw)]);
                b[nf][1] = f2tf(sB[cur][kr1 * BN + (n ^ sw)]);
            }
#pragma unroll
            for (int mf = 0; mf < 2; mf++)
#pragma unroll
                for (int nf = 0; nf < 4; nf++)
                    MMA8(acc[mf][nf], a[mf], b[nf]);
        }
        __syncthreads();
    }

#pragma unroll
    for (int mf = 0; mf < 2; mf++) {
        int r0 = bm + wm + mf * 16 + g, r1 = r0 + 8;
#pragma unroll
        for (int nf = 0; nf < 4; nf++) {
            int cn = wn + nf * 8 + t * 2;
            if (r0 < M) {
                float2 v = make_float2(acc[mf][nf][0], acc[mf][nf][1]);
                *reinterpret_cast<float2*>(C + (size_t)r0 * 64 + cn) = v;
            }
            if (r1 < M) {
                float2 v = make_float2(acc[mf][nf][2], acc[mf][nf][3]);
                *reinterpret_cast<float2*>(C + (size_t)r1 * 64 + cn) = v;
            }
        }
    }
}

// ---------------- bf16 tensor-core GEMM core (scalar-LDS fragments, 3-stage) -----
#define BN2 128
#define BKB 32
#define NST 3

#define MMA16(d, a, b) asm volatile( \
    "mma.sync.aligned.m16n8k16.row.col.f32.bf16.bf16.f32 " \
    "{%0,%1,%2,%3}, {%4,%5,%6,%7}, {%8,%9}, {%0,%1,%2,%3};" \
    : "+f"(d[0]), "+f"(d[1]), "+f"(d[2]), "+f"(d[3]) \
    : "r"(a[0]), "r"(a[1]), "r"(a[2]), "r"(a[3]), "r"(b[0]), "r"(b[1]))

struct MmaCtx {
    int tid, bm, bn, wm, wn, g, t;
};

__device__ __forceinline__ void bf16_mainloop(
    const __nv_bfloat16* __restrict__ A, const __nv_bfloat16* __restrict__ Bt,
    int M, int K, int lda, const MmaCtx& cx,
    uint32_t (*sA)[BM * 16], uint32_t (*sB)[BN2 * 16],
    float acc[2][8][4])
{
    const int tid = cx.tid, bm = cx.bm, bn = cx.bn;
    const int wm = cx.wm, wn = cx.wn, g = cx.g, t = cx.t;

    const int nK = K / BKB;

    auto loadA = [&](int kt, int s) {
#pragma unroll
        for (int p = 0; p < 2; p++) {
            int idx = tid + p * 256;
            int m = idx >> 2, c4 = idx & 3;
            int gm = bm + m;
            int valid = (gm < M) ? 16 : 0;
            const __nv_bfloat16* src = (valid > 0)
                ? (A + (size_t)gm * lda + kt * BKB + c4 * 8) : A;
            unsigned dst = (unsigned)__cvta_generic_to_shared(
                &sA[s][m * 16 + (c4 ^ ((m >> 1) & 3)) * 4]);
            cp16(dst, src, valid);
        }
    };
    auto loadB = [&](int kt, int s) {
#pragma unroll
        for (int p = 0; p < 2; p++) {
            int idx = tid + p * 256;
            int n = idx >> 2, c4 = idx & 3;
            const __nv_bfloat16* src = Bt + (size_t)(bn + n) * K + kt * BKB + c4 * 8;
            unsigned dst = (unsigned)__cvta_generic_to_shared(
                &sB[s][n * 16 + (c4 ^ ((n >> 1) & 3)) * 4]);
            cp16(dst, src, 16);
        }
    };

    loadA(0, 0); loadB(0, 0);
    asm volatile("cp.async.commit_group;");
    if (1 < nK) {
        loadA(1, 1); loadB(1, 1);
        asm volatile("cp.async.commit_group;");
    }

    int s_comp = 0, s_load = 2;

    for (int kt = 0; kt < nK; kt++) {
        if (kt == nK - 1) { asm volatile("cp.async.wait_group 0;"); }
        else              { asm volatile("cp.async.wait_group 1;"); }
        __syncthreads();

        if (kt + 2 < nK) {
            loadA(kt + 2, s_load); loadB(kt + 2, s_load);
            asm volatile("cp.async.commit_group;");
            if (++s_load == NST) s_load = 0;
        }

        int cur = s_comp;
#pragma unroll
        for (int ks = 0; ks < 2; ks++) {
            uint32_t a[2][4], b[8][2];
            int w0 = t + ks * 8, w1 = t + 4 + ks * 8;
#pragma unroll
            for (int mf = 0; mf < 2; mf++) {
                int r0 = wm + mf * 16 + g, r1 = r0 + 8;
                int s0 = ((r0 >> 1) & 3) << 2;
                a[mf][0] = sA[cur][r0 * 16 + (w0 ^ s0)];
                a[mf][1] = sA[cur][r1 * 16 + (w0 ^ s0)];
                a[mf][2] = sA[cur][r0 * 16 + (w1 ^ s0)];
                a[mf][3] = sA[cur][r1 * 16 + (w1 ^ s0)];
            }
#pragma unroll
            for (int nf = 0; nf < 8; nf++) {
                int n0 = wn + nf * 8 + g;
                int sn = ((n0 >> 1) & 3) << 2;
                b[nf][0] = sB[cur][n0 * 16 + (w0 ^ sn)];
                b[nf][1] = sB[cur][n0 * 16 + (w1 ^ sn)];
            }
#pragma unroll
            for (int mf = 0; mf < 2; mf++)
#pragma unroll
                for (int nf = 0; nf < 8; nf++)
                    MMA16(acc[mf][nf], a[mf], b[nf]);
        }
        if (++s_comp == NST) s_comp = 0;
        __syncthreads();
    }
}

// ---------------- MEGA kernel: node GEMM + att logits + ec conversion ------------
#define MB_N ((NNODES + BM - 1) / BM)          // 157
#define MB_E ((NEDGES + BM - 1) / BM)          // 782
#define SEG0 (2 * (AEMB / BN2) * MB_N)         // 3140 node value blocks
#define SEG1 (2 * MB_N)                        // 314 node logit blocks
#define SEG2 MB_E                              // 782 edge logit blocks
#define ECB_BLOCKS 1480                        // streaming conversion blocks
#define MEGA_BLOCKS (SEG0 + SEG1 + SEG2 + ECB_BLOCKS)

__global__ __launch_bounds__(256, 2) void k_mega(
    const __nv_bfloat16* __restrict__ hb,
    const __nv_bfloat16* __restrict__ Wt1, const __nv_bfloat16* __restrict__ Wt2,
    __nv_bfloat16* __restrict__ G1, __nv_bfloat16* __restrict__ G2,
    const float* __restrict__ h, const float* __restrict__ ec,
    const float* __restrict__ Wap1, const float* __restrict__ Wap2,
    const float* __restrict__ Wape,
    float* __restrict__ a1, float* __restrict__ a2, float* __restrict__ ae,
    float* __restrict__ out_ec)
{
    __shared__ __align__(16) uint8_t s_raw[49152];
    const int bid = blockIdx.x;

    if (bid < SEG0) {
        // ---- node value GEMM (bf16, both W slices) ----
        uint32_t (*sA)[BM * 16] = reinterpret_cast<uint32_t(*)[BM * 16]>(s_raw);
        uint32_t (*sB)[BN2 * 16] = reinterpret_cast<uint32_t(*)[BN2 * 16]>(s_raw + 24576);
        const int half = AEMB / BN2;   // 10
        int bx = bid % (2 * half), by = bid / (2 * half);
        const __nv_bfloat16* Bt = (bx < half) ? Wt1 : Wt2;
        __nv_bfloat16* C = (bx < half) ? G1 : G2;

        MmaCtx cx;
        cx.tid = threadIdx.x;
        cx.bm = by * BM;
        cx.bn = (bx % half) * BN2;
        int w = cx.tid >> 5, lane = cx.tid & 31;
        cx.wm = (w >> 1) * 32; cx.wn = (w & 1) * 64;
        cx.g = lane >> 2; cx.t = lane & 3;

        float acc[2][8][4];
#pragma unroll
        for (int mf = 0; mf < 2; mf++)
#pragma unroll
            for (int nf = 0; nf < 8; nf++)
#pragma unroll
                for (int q = 0; q < 4; q++) acc[mf][nf][q] = 0.f;

        bf16_mainloop(hb, Bt, NNODES, DNODE, DNODE, cx, sA, sB, acc);

#pragma unroll
        for (int mf = 0; mf < 2; mf++) {
            int r0 = cx.bm + cx.wm + mf * 16 + cx.g, r1 = r0 + 8;
#pragma unroll
            for (int nf = 0; nf < 8; nf++) {
                int cn = cx.bn + cx.wn + nf * 8 + cx.t * 2;
                if (r0 < NNODES) {
                    __nv_bfloat162 v;
                    v.x = __float2bfloat16(acc[mf][nf][0]);
                    v.y = __float2bfloat16(acc[mf][nf][1]);
                    *reinterpret_cast<__nv_bfloat162*>(C + (size_t)r0 * AEMB + cn) = v;
                }
                if (r1 < NNODES) {
                    __nv_bfloat162 v;
                    v.x = __float2bfloat16(acc[mf][nf][2]);
                    v.y = __float2bfloat16(acc[mf][nf][3]);
                    *reinterpret_cast<__nv_bfloat162*>(C + (size_t)r1 * AEMB + cn) = v;
                }
            }
        }
    } else if (bid < SEG0 + SEG1) {
        // ---- node att logits (tf32, dual) ----
        float (*sA)[BM * BK] = reinterpret_cast<float(*)[BM * BK]>(s_raw);
        float (*sB)[BK * BN] = reinterpret_cast<float(*)[BK * BN]>(s_raw + 32768);
        int i = bid - SEG0;
        int bx = i & 1, by = i >> 1;
        const float* B = bx ? Wap2 : Wap1;
        float* C = bx ? a2 : a1;
        tf32_body<true>(h, B, C, NNODES, DNODE, DNODE, by * BM, sA, sB);
    } else if (bid < SEG0 + SEG1 + SEG2) {
        // ---- edge att logits (tf32, direct unpadded ec via cp4) ----
        float (*sA)[BM * BK] = reinterpret_cast<float(*)[BM * BK]>(s_raw);
        float (*sB)[BK * BN] = reinterpret_cast<float(*)[BK * BN]>(s_raw + 32768);
        int by = bid - SEG0 - SEG1;
        tf32_body<false>(ec, Wape, ae, NEDGES, DEDGE, DEDGE, by * BM, sA, sB);
    } else {
        // ---- edge_core conversion + passthrough (grid-stride streaming) ----
        int b = bid - SEG0 - SEG1 - SEG2;
        const int total = NEDGES * (DEDGE_PAD / 2);
        for (int t = threadIdx.x + b * 256; t < total; t += ECB_BLOCKS * 256) {
            int e = t >> 8, p = t & 255;
            int c = p * 2;
            const float* row = ec + (size_t)e * DEDGE;
            float x = (c     < DEDGE) ? row[c]     : 0.f;
            float y = (c + 1 < DEDGE) ? row[c + 1] : 0.f;
            __nv_bfloat162 v; v.x = __float2bfloat16(x); v.y = __float2bfloat16(y);
            *reinterpret_cast<__nv_bfloat162*>(g_ecb + (size_t)e * DEDGE_PAD + c) = v;
            float* orow = out_ec + (size_t)e * DEDGE;
            if (c < DEDGE)     orow[c] = x;
            if (c + 1 < DEDGE) orow[c + 1] = y;
        }
    }
}

// fused edge value GEMM + gelu + att-weighted pooling
__global__ __launch_bounds__(256, 2) void k_mma_edge_pool(
    const __nv_bfloat16* __restrict__ A, const __nv_bfloat16* __restrict__ Bt,
    const float* __restrict__ b_node, const float* __restrict__ att,
    int M, int K, int lda)
{
    __shared__ uint32_t sA[NST][BM * 16];
    __shared__ uint32_t sB[NST][BN2 * 16];
    MmaCtx cx;
    cx.tid = threadIdx.x;
    cx.bm = blockIdx.y * BM; cx.bn = blockIdx.x * BN2;
    int w = cx.tid >> 5, lane = cx.tid & 31;
    cx.wm = (w >> 1) * 32; cx.wn = (w & 1) * 64;
    cx.g = lane >> 2; cx.t = lane & 3;

    float acc[2][8][4];
#pragma unroll
    for (int mf = 0; mf < 2; mf++)
#pragma unroll
        for (int nf = 0; nf < 8; nf++)
#pragma unroll
            for (int q = 0; q < 4; q++) acc[mf][nf][q] = 0.f;

    bf16_mainloop(A, Bt, M, K, lda, cx, sA, sB, acc);

    const int head = (cx.bn + cx.wn) >> 6;
    float colsum[16];
#pragma unroll
    for (int q = 0; q < 16; q++) colsum[q] = 0.f;

#pragma unroll
    for (int mf = 0; mf < 2; mf++) {
#pragma unroll
        for (int rr = 0; rr < 2; rr++) {
            int e = cx.bm + cx.wm + mf * 16 + cx.g + rr * 8;
            if (e < M) {
                int i = g_src[e], j = g_dst[e];
                float wv = __ldg(att + (size_t)e * NH + head);
                const __nv_bfloat162* P1 =
                    reinterpret_cast<const __nv_bfloat162*>(g_G1b + (size_t)i * AEMB);
                const __nv_bfloat162* P2 =
                    reinterpret_cast<const __nv_bfloat162*>(g_G2b + (size_t)j * AEMB);
#pragma unroll
                for (int nf = 0; nf < 8; nf++) {
                    int cn = cx.bn + cx.wn + nf * 8 + cx.t * 2;
                    float2 v1 = __bfloat1622float2(P1[cn >> 1]);
                    float2 v2 = __bfloat1622float2(P2[cn >> 1]);
                    float x = acc[mf][nf][rr * 2]     + v1.x + v2.x + __ldg(b_node + cn);
                    float y = acc[mf][nf][rr * 2 + 1] + v1.y + v2.y + __ldg(b_node + cn + 1);
                    float gx = 0.5f * x * (1.f + erff(x * 0.70710678118654752f));
                    float gy = 0.5f * y * (1.f + erff(y * 0.70710678118654752f));
                    colsum[nf * 2]     += wv * gx;
                    colsum[nf * 2 + 1] += wv * gy;
                }
            }
        }
    }

#pragma unroll
    for (int q = 0; q < 16; q++) {
        colsum[q] += __shfl_down_sync(0xffffffffu, colsum[q], 16);
        colsum[q] += __shfl_down_sync(0xffffffffu, colsum[q], 8);
        colsum[q] += __shfl_down_sync(0xffffffffu, colsum[q], 4);
    }
    if (lane < 4) {
#pragma unroll
        for (int nf = 0; nf < 8; nf++) {
            int cn = cx.bn + cx.wn + nf * 8 + cx.t * 2;
            atomicAdd(&g_gf[cn],     colsum[nf * 2]);
            atomicAdd(&g_gf[cn + 1], colsum[nf * 2 + 1]);
        }
    }
}

// ---------------- attention logits + softmax ----------------
__global__ void k_logits(const float* __restrict__ b_att) {
    int e = blockIdx.x * blockDim.x + threadIdx.x;
    if (e >= NEDGES) return;
    int i = g_src[e], j = g_dst[e];
    const float* p1 = g_a1 + (size_t)i * 64;
    const float* p2 = g_a2 + (size_t)j * 64;
    const float* pe = g_ae + (size_t)e * 64;
    float* pw = g_w + (size_t)e * NH;
#pragma unroll
    for (int h = 0; h < NH; h++) {
        float v = p1[h] + pe[h] + p2[h] + b_att[h];
        v = v > 0.f ? v : 0.f;
        pw[h] = v * 0.125f;
    }
}

__global__ void k_softmax_stats() {
    int h = blockIdx.x, t = threadIdx.x;
    __shared__ float sm[256];
    float m = -1e30f;
    for (int e = t; e < NEDGES; e += 256) m = fmaxf(m, g_w[(size_t)e * NH + h]);
    sm[t] = m; __syncthreads();
    for (int s = 128; s > 0; s >>= 1) { if (t < s) sm[t] = fmaxf(sm[t], sm[t + s]); __syncthreads(); }
    float mm = sm[0]; __syncthreads();
    float s = 0.f;
    for (int e = t; e < NEDGES; e += 256) s += expf(g_w[(size_t)e * NH + h] - mm);
    sm[t] = s; __syncthreads();
    for (int st = 128; st > 0; st >>= 1) { if (t < st) sm[t] += sm[t + st]; __syncthreads(); }
    if (t == 0) { g_smax[h] = mm; g_sden[h] = sm[0]; }
}

__global__ void k_att_write(float* __restrict__ att_out) {
    int t = blockIdx.x * blockDim.x + threadIdx.x;
    if (t >= NEDGES * NH) return;
    int h = t % NH;
    att_out[t] = expf(g_w[t] - g_smax[h]) / g_sden[h];
}

// ---------------- FFN head ----------------
__global__ void k_ffn1(const float* __restrict__ W1, const float* __restrict__ b1) {
    int n = blockIdx.x * blockDim.x + threadIdx.x;
    if (n >= FF) return;
    float acc = 0.f;
#pragma unroll 4
    for (int k = 0; k < AEMB; k++) acc += g_gf[k] * __ldg(W1 + (size_t)k * FF + n);
    float v = acc + b1[n];
    g_y1[n] = v > 0.f ? v : 0.f;
}

__global__ void k_ffn2(const float* __restrict__ W2, const float* __restrict__ b2) {
    int n = blockIdx.x * blockDim.x + threadIdx.x;
    if (n >= AEMB) return;
    float acc = 0.f;
#pragma unroll 4
    for (int k = 0; k < FF; k++) acc += g_y1[k] * __ldg(W2 + (size_t)k * AEMB + n);
    g_y2[n] = acc + b2[n];
}

__global__ void k_ffn3(const float* __restrict__ Wh, float* __restrict__ out_gf) {
    int n = blockIdx.x * blockDim.x + threadIdx.x;
    if (n >= AEMB) return;
    float acc = 0.f;
#pragma unroll 4
    for (int k = 0; k < AEMB; k++) acc += g_y2[k] * __ldg(Wh + (size_t)k * AEMB + n);
    out_gf[n] = acc;
}

// ---------------- launch ----------------
extern "C" void kernel_launch(void* const* d_in, const int* in_sizes, int n_in,
                              void* d_out, int out_size)
{
    const float* h      = (const float*)d_in[0];
    const float* ec     = (const float*)d_in[1];
    const int*   idxraw = (const int*)  d_in[2];
    const float* W_att  = (const float*)d_in[3];
    const float* b_att  = (const float*)d_in[4];
    const float* W_node = (const float*)d_in[5];
    const float* b_node = (const float*)d_in[6];
    const float* W1     = (const float*)d_in[7];
    const float* b1     = (const float*)d_in[8];
    const float* W2     = (const float*)d_in[9];
    const float* b2     = (const float*)d_in[10];
    const float* Wh     = (const float*)d_in[11];

    float* out     = (float*)d_out;
    float* out_h   = out;
    float* out_ec  = out + (size_t)NNODES * DNODE;
    float* out_gf  = out_ec + (size_t)NEDGES * DEDGE;
    float* out_att = out_gf + AEMB;

    float *pa1, *pa2, *pae, *pWap1, *pWap2, *pWape;
    __nv_bfloat16 *pG1b, *pG2b, *phb, *pecb, *pWt1, *pWt2, *pWte;
    cudaGetSymbolAddress((void**)&pa1,  g_a1);
    cudaGetSymbolAddress((void**)&pa2,  g_a2);
    cudaGetSymbolAddress((void**)&pae,  g_ae);
    cudaGetSymbolAddress((void**)&pWap1, g_Wap1);
    cudaGetSymbolAddress((void**)&pWap2, g_Wap2);
    cudaGetSymbolAddress((void**)&pWape, g_Wape);
    cudaGetSymbolAddress((void**)&pG1b, g_G1b);
    cudaGetSymbolAddress((void**)&pG2b, g_G2b);
    cudaGetSymbolAddress((void**)&phb,  g_hb);
    cudaGetSymbolAddress((void**)&pecb, g_ecb);
    cudaGetSymbolAddress((void**)&pWt1, g_Wt1);
    cudaGetSymbolAddress((void**)&pWt2, g_Wt2);
    cudaGetSymbolAddress((void**)&pWte, g_Wte);

    // ---- prep (h passthrough fused into h2bf) ----
    k_h2bf<<<(NNODES * DNODE / 4 + 255) / 256, 256>>>(h, out_h);
    {
        dim3 blk(32, 8);
        k_wt<<<dim3(DNODE / 32, AEMB / 32), blk>>>(W_node, pWt1, DNODE, DNODE);
        k_wt<<<dim3(DNODE / 32, AEMB / 32), blk>>>(W_node + (size_t)(DNODE + DEDGE) * AEMB, pWt2, DNODE, DNODE);
        k_wt<<<dim3(DEDGE_PAD / 32, AEMB / 32), blk>>>(W_node + (size_t)DNODE * AEMB, pWte, DEDGE, DEDGE_PAD);
    }
    k_wap<<<(DNODE * 64 + 255) / 256, 256>>>(W_att);
    k_idx_mode<<<1, 32>>>(idxraw);
    k_cvt_idx<<<(NEDGES + 255) / 256, 256>>>(idxraw);
    k_zero_gf<<<(AEMB + 255) / 256, 256>>>();

    // ---- MEGA: node value GEMM + att logits + ec conversion, one launch ----
    k_mega<<<MEGA_BLOCKS, 256>>>(phb, pWt1, pWt2, pG1b, pG2b,
                                 h, ec, pWap1, pWap2, pWape,
                                 pa1, pa2, pae, out_ec);

    // ---- softmax path ----
    k_logits<<<(NEDGES + 255) / 256, 256>>>(b_att);
    k_softmax_stats<<<NH, 256>>>();
    k_att_write<<<(NEDGES * NH + 255) / 256, 256>>>(out_att);

    // ---- fused edge value GEMM + gelu + pooling ----
    k_mma_edge_pool<<<dim3(AEMB / BN2, (NEDGES + BM - 1) / BM), 256>>>(
        pecb, pWte, b_node, out_att, NEDGES, DEDGE_PAD, DEDGE_PAD);

    // ---- FFN head ----
    k_ffn1<<<(FF + 255) / 256, 256>>>(W1, b1);
    k_ffn2<<<(AEMB + 255) / 256, 256>>>(W2, b2);
    k_ffn3<<<(AEMB + 255) / 256, 256>>>(Wh, out_gf);
}